// round 5
// baseline (speedup 1.0000x reference)
#include <cuda_runtime.h>
#include <cuda_bf16.h>
#include <cstdint>
#include <math.h>

#define BATCH 4
#define HEADS 16
#define SEQ   2048
#define DKDIM 64
#define BH    (BATCH*HEADS)

// Softmax stats scratch (allowed: __device__ global array)
__device__ float g_M[BH * SEQ];
__device__ float g_L[BH * SEQ];

// ---------------------------------------------------------------------------
// Helpers: ldmatrix + mma.sync (sm_80+ ISA, valid on base sm_103 target)
// ---------------------------------------------------------------------------
__device__ __forceinline__ uint32_t smem_u32(const void* p) {
    uint32_t a;
    asm("{ .reg .u64 t; cvta.to.shared.u64 t, %1; cvt.u32.u64 %0, t; }"
        : "=r"(a) : "l"(p));
    return a;
}
__device__ __forceinline__ void ldsm_x4(uint32_t (&r)[4], uint32_t addr) {
    asm volatile("ldmatrix.sync.aligned.m8n8.x4.shared.b16 {%0,%1,%2,%3}, [%4];"
        : "=r"(r[0]), "=r"(r[1]), "=r"(r[2]), "=r"(r[3]) : "r"(addr));
}
__device__ __forceinline__ void ldsm_x4_t(uint32_t (&r)[4], uint32_t addr) {
    asm volatile("ldmatrix.sync.aligned.m8n8.x4.trans.shared.b16 {%0,%1,%2,%3}, [%4];"
        : "=r"(r[0]), "=r"(r[1]), "=r"(r[2]), "=r"(r[3]) : "r"(addr));
}
__device__ __forceinline__ void mma_bf16(float (&c)[4], const uint32_t (&a)[4],
                                         uint32_t b0, uint32_t b1) {
    asm volatile("mma.sync.aligned.m16n8k16.row.col.f32.bf16.bf16.f32 "
        "{%0,%1,%2,%3}, {%4,%5,%6,%7}, {%8,%9}, {%0,%1,%2,%3};"
        : "+f"(c[0]), "+f"(c[1]), "+f"(c[2]), "+f"(c[3])
        : "r"(a[0]), "r"(a[1]), "r"(a[2]), "r"(a[3]), "r"(b0), "r"(b1));
}

#define SW128(b) ((b) ^ (((b) >> 3) & 0x70))

__device__ __forceinline__ void split_bf16(float x, uint16_t& hi, uint16_t& lo) {
    __nv_bfloat16 h = __float2bfloat16(x);
    __nv_bfloat16 l = __float2bfloat16(x - __bfloat162float(h));
    hi = __bfloat16_as_ushort(h);
    lo = __bfloat16_as_ushort(l);
}

// ---------------------------------------------------------------------------
// Kernel 1: raw scores + online softmax stats.
// CTA: 128 q rows x full 2048 k (16 tiles of 128). 8 warps, warp = 16q x 128k.
// Writes masked scaled scores (raw) to attn region; (m, l) to g_M/g_L.
// SMEM: Qhi/Qlo [128x64 bf16] + Khi/Klo [128x64 bf16] = 64 KB.
// ---------------------------------------------------------------------------
#define S_QHI 0
#define S_QLO 16384
#define S_KHI 32768
#define S_KLO 49152
#define S_SMEM_TOTAL 65536

__global__ __launch_bounds__(256)
void scores_stats(const float* __restrict__ Q, const float* __restrict__ K,
                  const int* __restrict__ mask, float* __restrict__ attn)
{
    extern __shared__ char smem[];
    const int tid = threadIdx.x, wid = tid >> 5, lane = tid & 31;

    const int bh = blockIdx.y, b = bh >> 4;
    const int qBase = blockIdx.x * 128;

    const float* Qp = Q + (size_t)bh * SEQ * DKDIM;
    const float* Kp = K + (size_t)bh * SEQ * DKDIM;

    // Q tile [128 x 64] fp32 -> hi/lo bf16, SW128 rows of 128B (resident).
    #pragma unroll
    for (int i = tid; i < 4096; i += 256) {
        const int r = i >> 5, c2 = i & 31;
        float2 v = *(const float2*)&Qp[(size_t)(qBase + r) * DKDIM + c2 * 2];
        uint16_t h0, l0, h1, l1;
        split_bf16(v.x, h0, l0); split_bf16(v.y, h1, l1);
        const uint32_t sw = SW128((uint32_t)(r * 128 + c2 * 4));
        *(uint32_t*)(smem + S_QHI + sw) = (uint32_t)h0 | ((uint32_t)h1 << 16);
        *(uint32_t*)(smem + S_QLO + sw) = (uint32_t)l0 | ((uint32_t)l1 << 16);
    }

    const uint32_t qhi = smem_u32(smem + S_QHI), qlo = smem_u32(smem + S_QLO);
    const uint32_t khi = smem_u32(smem + S_KHI), klo = smem_u32(smem + S_KLO);

    const int wm   = wid * 16;            // warp q offset
    const int arow = lane & 15;
    const int abyt = (lane >> 4) << 4;
    const int row0 = lane >> 2;           // 0..7 (row within m16: +0 / +8)

    float m0 = -INFINITY, m1 = -INFINITY, l0 = 0.0f, l1 = 0.0f;

    const int* mp = mask + (size_t)b  * SEQ * SEQ;
    float*     ap = attn + (size_t)bh * SEQ * SEQ;

    for (int kt = 0; kt < SEQ; kt += 128) {
        // Convert K tile [128 x 64]
        #pragma unroll
        for (int i = tid; i < 4096; i += 256) {
            const int r = i >> 5, c2 = i & 31;
            float2 v = *(const float2*)&Kp[(size_t)(kt + r) * DKDIM + c2 * 2];
            uint16_t h0, lw0, h1, lw1;
            split_bf16(v.x, h0, lw0); split_bf16(v.y, h1, lw1);
            const uint32_t sw = SW128((uint32_t)(r * 128 + c2 * 4));
            *(uint32_t*)(smem + S_KHI + sw) = (uint32_t)h0  | ((uint32_t)h1  << 16);
            *(uint32_t*)(smem + S_KLO + sw) = (uint32_t)lw0 | ((uint32_t)lw1 << 16);
        }
        __syncthreads();

        float acc[16][4];
        #pragma unroll
        for (int j = 0; j < 16; j++)
            #pragma unroll
            for (int e = 0; e < 4; e++) acc[j][e] = 0.0f;

        #pragma unroll
        for (int t = 0; t < 3; t++) {
            const uint32_t ab = (t < 2) ? qhi : qlo;
            const uint32_t bb = (t == 1) ? klo : khi;
            #pragma unroll
            for (int ks = 0; ks < 4; ks++) {
                uint32_t a[4];
                ldsm_x4(a, ab + SW128((uint32_t)((wm + arow) * 128 + ks * 32 + abyt)));
                #pragma unroll
                for (int nj = 0; nj < 8; nj++) {
                    uint32_t bf[4];
                    ldsm_x4(bf, bb + SW128((uint32_t)((nj * 16 + arow) * 128 + ks * 32 + abyt)));
                    mma_bf16(acc[nj * 2],     a, bf[0], bf[2]);
                    mma_bf16(acc[nj * 2 + 1], a, bf[1], bf[3]);
                }
            }
        }

        // Mask + scale + store raw, track tile max.
        const int r0g = qBase + wm + row0;
        float tmx0 = -INFINITY, tmx1 = -INFINITY;
        #pragma unroll
        for (int j = 0; j < 16; j++) {
            const int col = kt + j * 8 + (lane & 3) * 2;
            const size_t o0 = (size_t)r0g * SEQ + col;
            const size_t o1 = o0 + (size_t)8 * SEQ;
            int2 ma = *(const int2*)&mp[o0];
            int2 mb = *(const int2*)&mp[o1];
            acc[j][0] = ma.x ? acc[j][0] * 0.125f : -1e9f;
            acc[j][1] = ma.y ? acc[j][1] * 0.125f : -1e9f;
            acc[j][2] = mb.x ? acc[j][2] * 0.125f : -1e9f;
            acc[j][3] = mb.y ? acc[j][3] * 0.125f : -1e9f;
            *(float2*)&ap[o0] = make_float2(acc[j][0], acc[j][1]);
            *(float2*)&ap[o1] = make_float2(acc[j][2], acc[j][3]);
            tmx0 = fmaxf(tmx0, fmaxf(acc[j][0], acc[j][1]));
            tmx1 = fmaxf(tmx1, fmaxf(acc[j][2], acc[j][3]));
        }
        // quad reduce (lanes sharing a row differ only in lane&3)
        tmx0 = fmaxf(tmx0, __shfl_xor_sync(0xffffffffu, tmx0, 1));
        tmx0 = fmaxf(tmx0, __shfl_xor_sync(0xffffffffu, tmx0, 2));
        tmx1 = fmaxf(tmx1, __shfl_xor_sync(0xffffffffu, tmx1, 1));
        tmx1 = fmaxf(tmx1, __shfl_xor_sync(0xffffffffu, tmx1, 2));

        const float m0n = fmaxf(m0, tmx0);
        const float m1n = fmaxf(m1, tmx1);
        float s0 = 0.0f, s1 = 0.0f;
        #pragma unroll
        for (int j = 0; j < 16; j++) {
            s0 += __expf(acc[j][0] - m0n) + __expf(acc[j][1] - m0n);
            s1 += __expf(acc[j][2] - m1n) + __expf(acc[j][3] - m1n);
        }
        s0 += __shfl_xor_sync(0xffffffffu, s0, 1);
        s0 += __shfl_xor_sync(0xffffffffu, s0, 2);
        s1 += __shfl_xor_sync(0xffffffffu, s1, 1);
        s1 += __shfl_xor_sync(0xffffffffu, s1, 2);

        l0 = l0 * __expf(m0 - m0n) + s0;  m0 = m0n;
        l1 = l1 * __expf(m1 - m1n) + s1;  m1 = m1n;

        __syncthreads();   // before overwriting K smem
    }

    if ((lane & 3) == 0) {
        const int r0g = qBase + wm + row0;
        g_M[(size_t)bh * SEQ + r0g]     = m0;
        g_L[(size_t)bh * SEQ + r0g]     = l0;
        g_M[(size_t)bh * SEQ + r0g + 8] = m1;
        g_L[(size_t)bh * SEQ + r0g + 8] = l1;
    }
}

// ---------------------------------------------------------------------------
// Kernel 2: normalize attn in place + out = attn . V  (split-bf16 mma.sync)
// CTA: 128 q x 64 d; K = 2048 in 32 tiles of 64. Warp tile 32m x 32n (4x2).
// ---------------------------------------------------------------------------
#define O_PHI 0
#define O_PLO 16384
#define O_VHI 32768
#define O_VLO 40960
#define O_M   49152
#define O_IL  (49152 + 512)
#define O_SMEM_TOTAL (49152 + 1024)

__global__ __launch_bounds__(256)
void out_norm_tc(float* __restrict__ attn, const float* __restrict__ V,
                 float* __restrict__ out)
{
    extern __shared__ char smem[];
    const int tid = threadIdx.x, wid = tid >> 5, lane = tid & 31;

    const int bh = blockIdx.y;
    const int qBase = blockIdx.x * 128;

    float* ap = attn + (size_t)bh * SEQ * SEQ;
    const float* Vp = V + (size_t)bh * SEQ * DKDIM;

    float* sm_m  = (float*)(smem + O_M);
    float* sm_il = (float*)(smem + O_IL);
    if (tid < 128) {
        sm_m[tid]  = g_M[(size_t)bh * SEQ + qBase + tid];
        sm_il[tid] = 1.0f / g_L[(size_t)bh * SEQ + qBase + tid];
    }
    __syncthreads();

    const int wm = (wid >> 1) * 32;
    const int wn = (wid & 1) * 32;

    float acc[2][4][4];
    #pragma unroll
    for (int mi = 0; mi < 2; mi++)
        #pragma unroll
        for (int nj = 0; nj < 4; nj++)
            #pragma unroll
            for (int e = 0; e < 4; e++) acc[mi][nj][e] = 0.0f;

    const uint32_t phi = smem_u32(smem + O_PHI), plo = smem_u32(smem + O_PLO);
    const uint32_t vhi = smem_u32(smem + O_VHI), vlo = smem_u32(smem + O_VLO);

    const int arow = lane & 15;
    const int abyt = (lane >> 4) << 4;

    for (int kt = 0; kt < SEQ; kt += 64) {
        // Read raw score tile [128 x 64], normalize, write back, split to smem.
        #pragma unroll
        for (int j = 0; j < 8; j++) {
            const int idx = tid + j * 256;          // 0..2047 float4 slots
            const int r   = idx >> 4;               // row 0..127
            const int c4  = idx & 15;               // float4 col 0..15
            float4 v = *(const float4*)&ap[(size_t)(qBase + r) * SEQ + kt + c4 * 4];
            const float mr = sm_m[r], il = sm_il[r];
            v.x = __expf(v.x - mr) * il;
            v.y = __expf(v.y - mr) * il;
            v.z = __expf(v.z - mr) * il;
            v.w = __expf(v.w - mr) * il;
            *(float4*)&ap[(size_t)(qBase + r) * SEQ + kt + c4 * 4] = v;
            uint16_t h0, l0, h1, l1, h2, l2, h3, l3;
            split_bf16(v.x, h0, l0); split_bf16(v.y, h1, l1);
            split_bf16(v.z, h2, l2); split_bf16(v.w, h3, l3);
            const uint32_t sw = SW128((uint32_t)(r * 128 + c4 * 8));
            *(uint32_t*)(smem + O_PHI + sw)     = (uint32_t)h0 | ((uint32_t)h1 << 16);
            *(uint32_t*)(smem + O_PHI + sw + 4) = (uint32_t)h2 | ((uint32_t)h3 << 16);
            *(uint32_t*)(smem + O_PLO + sw)     = (uint32_t)l0 | ((uint32_t)l1 << 16);
            *(uint32_t*)(smem + O_PLO + sw + 4) = (uint32_t)l2 | ((uint32_t)l3 << 16);
        }
        // V tile [64 k x 64 d] natural rows (128B), split bf16.
        #pragma unroll
        for (int i = tid; i < 2048; i += 256) {
            const int k = i >> 5, d2 = i & 31;
            float2 v = *(const float2*)&Vp[(size_t)(kt + k) * DKDIM + d2 * 2];
            uint16_t h0, l0, h1, l1;
            split_bf16(v.x, h0, l0); split_bf16(v.y, h1, l1);
            const uint32_t sw = SW128((uint32_t)(k * 128 + d2 * 4));
            *(uint32_t*)(smem + O_VHI + sw) = (uint32_t)h0 | ((uint32_t)h1 << 16);
            *(uint32_t*)(smem + O_VLO + sw) = (uint32_t)l0 | ((uint32_t)l1 << 16);
        }
        __syncthreads();

        #pragma unroll
        for (int t = 0; t < 3; t++) {
            const uint32_t ab = (t < 2) ? phi : plo;
            const uint32_t bb = (t == 1) ? vlo : vhi;
            #pragma unroll
            for (int ks = 0; ks < 4; ks++) {
                uint32_t a[2][4];
                #pragma unroll
                for (int mi = 0; mi < 2; mi++)
                    ldsm_x4(a[mi], ab + SW128((uint32_t)((wm + mi*16 + arow) * 128 + ks*32 + abyt)));
                #pragma unroll
                for (int nj = 0; nj < 2; nj++) {
                    uint32_t bf[4];
                    ldsm_x4_t(bf, bb + SW128((uint32_t)((ks*16 + arow) * 128 + (wn + nj*16)*2 + abyt)));
                    #pragma unroll
                    for (int mi = 0; mi < 2; mi++) {
                        mma_bf16(acc[mi][nj*2],     a[mi], bf[0], bf[1]);
                        mma_bf16(acc[mi][nj*2 + 1], a[mi], bf[2], bf[3]);
                    }
                }
            }
        }
        __syncthreads();
    }

    float* op = out + (size_t)bh * SEQ * DKDIM;
    #pragma unroll
    for (int mi = 0; mi < 2; mi++) {
        const int r0 = qBase + wm + mi * 16 + (lane >> 2);
        #pragma unroll
        for (int nj = 0; nj < 4; nj++) {
            const int col = wn + nj * 8 + (lane & 3) * 2;
            float2 w0 = {acc[mi][nj][0], acc[mi][nj][1]};
            float2 w1 = {acc[mi][nj][2], acc[mi][nj][3]};
            *(float2*)&op[(size_t)r0 * DKDIM + col]       = w0;
            *(float2*)&op[(size_t)(r0 + 8) * DKDIM + col] = w1;
        }
    }
}

// ---------------------------------------------------------------------------
extern "C" void kernel_launch(void* const* d_in, const int* in_sizes, int n_in,
                              void* d_out, int out_size)
{
    const float* Q    = (const float*)d_in[0];
    const float* K    = (const float*)d_in[1];
    const float* V    = (const float*)d_in[2];
    const int*   mask = (const int*)  d_in[3];

    float* out  = (float*)d_out;
    float* attn = out + (size_t)BH * SEQ * DKDIM;

    cudaFuncSetAttribute(scores_stats, cudaFuncAttributeMaxDynamicSharedMemorySize, S_SMEM_TOTAL);
    cudaFuncSetAttribute(out_norm_tc,  cudaFuncAttributeMaxDynamicSharedMemorySize, O_SMEM_TOTAL);

    scores_stats<<<dim3(SEQ / 128, BH), 256, S_SMEM_TOTAL>>>(Q, K, mask, attn);
    out_norm_tc<<<dim3(SEQ / 128, BH), 256, O_SMEM_TOTAL>>>(attn, V, out);
}

// round 6
// speedup vs baseline: 1.3928x; 1.3928x over previous
#include <cuda_runtime.h>
#include <cuda_bf16.h>
#include <cstdint>
#include <math.h>

#define BATCH 4
#define HEADS 16
#define SEQ   2048
#define DKDIM 64
#define BH    (BATCH*HEADS)
#define NELEM (BH*SEQ*DKDIM)   // 8,388,608

// Scratch (allowed: __device__ global arrays)
__device__ float g_M[BH * SEQ];
__device__ float g_L[BH * SEQ];
__device__ __nv_bfloat16 g_Qhi[NELEM], g_Qlo[NELEM];
__device__ __nv_bfloat16 g_Khi[NELEM], g_Klo[NELEM];
__device__ __nv_bfloat16 g_Vhi[NELEM], g_Vlo[NELEM];

// ---------------------------------------------------------------------------
// PTX helpers
// ---------------------------------------------------------------------------
__device__ __forceinline__ uint32_t smem_u32(const void* p) {
    uint32_t a;
    asm("{ .reg .u64 t; cvta.to.shared.u64 t, %1; cvt.u32.u64 %0, t; }"
        : "=r"(a) : "l"(p));
    return a;
}
__device__ __forceinline__ void ldsm_x4(uint32_t (&r)[4], uint32_t addr) {
    asm volatile("ldmatrix.sync.aligned.m8n8.x4.shared.b16 {%0,%1,%2,%3}, [%4];"
        : "=r"(r[0]), "=r"(r[1]), "=r"(r[2]), "=r"(r[3]) : "r"(addr));
}
__device__ __forceinline__ void ldsm_x4_t(uint32_t (&r)[4], uint32_t addr) {
    asm volatile("ldmatrix.sync.aligned.m8n8.x4.trans.shared.b16 {%0,%1,%2,%3}, [%4];"
        : "=r"(r[0]), "=r"(r[1]), "=r"(r[2]), "=r"(r[3]) : "r"(addr));
}
__device__ __forceinline__ void mma_bf16(float (&c)[4], const uint32_t (&a)[4],
                                         uint32_t b0, uint32_t b1) {
    asm volatile("mma.sync.aligned.m16n8k16.row.col.f32.bf16.bf16.f32 "
        "{%0,%1,%2,%3}, {%4,%5,%6,%7}, {%8,%9}, {%0,%1,%2,%3};"
        : "+f"(c[0]), "+f"(c[1]), "+f"(c[2]), "+f"(c[3])
        : "r"(a[0]), "r"(a[1]), "r"(a[2]), "r"(a[3]), "r"(b0), "r"(b1));
}
#define CP16(dst, src) \
    asm volatile("cp.async.cg.shared.global [%0], [%1], 16;" \
                 :: "r"(dst), "l"(src) : "memory")
#define CP_COMMIT  asm volatile("cp.async.commit_group;" ::: "memory")
#define CP_WAIT0   asm volatile("cp.async.wait_group 0;" ::: "memory")
#define CP_WAIT1   asm volatile("cp.async.wait_group 1;" ::: "memory")

#define SW128(b) ((b) ^ (((b) >> 3) & 0x70))

__device__ __forceinline__ void split_bf16(float x, uint16_t& hi, uint16_t& lo) {
    __nv_bfloat16 h = __float2bfloat16(x);
    __nv_bfloat16 l = __float2bfloat16(x - __bfloat162float(h));
    hi = __bfloat16_as_ushort(h);
    lo = __bfloat16_as_ushort(l);
}

// ---------------------------------------------------------------------------
// Kernel 0: preconvert Q, K, V fp32 -> split bf16 hi/lo arrays.
// ---------------------------------------------------------------------------
__global__ void preconv(const float* __restrict__ Q, const float* __restrict__ K,
                        const float* __restrict__ V)
{
    const int n2 = NELEM / 2;
    uint32_t* qh = (uint32_t*)g_Qhi; uint32_t* ql = (uint32_t*)g_Qlo;
    uint32_t* kh = (uint32_t*)g_Khi; uint32_t* kl = (uint32_t*)g_Klo;
    uint32_t* vh = (uint32_t*)g_Vhi; uint32_t* vl = (uint32_t*)g_Vlo;
    for (int i = blockIdx.x * blockDim.x + threadIdx.x; i < n2;
         i += gridDim.x * blockDim.x) {
        float2 q = ((const float2*)Q)[i];
        float2 k = ((const float2*)K)[i];
        float2 v = ((const float2*)V)[i];
        uint16_t h0, l0, h1, l1;
        split_bf16(q.x, h0, l0); split_bf16(q.y, h1, l1);
        qh[i] = (uint32_t)h0 | ((uint32_t)h1 << 16);
        ql[i] = (uint32_t)l0 | ((uint32_t)l1 << 16);
        split_bf16(k.x, h0, l0); split_bf16(k.y, h1, l1);
        kh[i] = (uint32_t)h0 | ((uint32_t)h1 << 16);
        kl[i] = (uint32_t)l0 | ((uint32_t)l1 << 16);
        split_bf16(v.x, h0, l0); split_bf16(v.y, h1, l1);
        vh[i] = (uint32_t)h0 | ((uint32_t)h1 << 16);
        vl[i] = (uint32_t)l0 | ((uint32_t)l1 << 16);
    }
}

// ---------------------------------------------------------------------------
// Kernel 1: raw scores + online softmax stats.
// CTA: 128 threads (4 warps), 64 q rows x full 2048 k (16 tiles of 128).
// Warp tile: 16q x 128k. K tiles cp.async double-buffered. SMEM 80 KB.
// ---------------------------------------------------------------------------
#define K1_QHI 0
#define K1_QLO 8192
#define K1_KHI 16384    // + buf*16384  (bufs at 16384, 32768)
#define K1_KLO 49152    // + buf*16384  (bufs at 49152, 65536)
#define K1_SMEM 81920

__global__ __launch_bounds__(128)
void scores_stats(const int* __restrict__ mask, float* __restrict__ attn)
{
    extern __shared__ char smem[];
    const uint32_t sb = smem_u32(smem);
    const int tid = threadIdx.x, wid = tid >> 5, lane = tid & 31;

    const int bh = blockIdx.y, b = bh >> 4;
    const int qBase = blockIdx.x * 64;

    // Q tile (resident): 64 rows x 128B, hi + lo
    const char* qhig = (const char*)(g_Qhi + (size_t)(bh * SEQ + qBase) * DKDIM);
    const char* qlog = (const char*)(g_Qlo + (size_t)(bh * SEQ + qBase) * DKDIM);
    #pragma unroll
    for (int i = tid; i < 512; i += 128) {
        const int r = i >> 3, c = i & 7;
        const uint32_t sw = SW128((uint32_t)(r * 128 + c * 16));
        CP16(sb + K1_QHI + sw, qhig + r * 128 + c * 16);
        CP16(sb + K1_QLO + sw, qlog + r * 128 + c * 16);
    }
    CP_COMMIT;

    const char* khig = (const char*)(g_Khi + (size_t)bh * SEQ * DKDIM);
    const char* klog = (const char*)(g_Klo + (size_t)bh * SEQ * DKDIM);

    auto issueK = [&](int kt, int buf) {
        #pragma unroll
        for (int i = tid; i < 1024; i += 128) {
            const int r = i >> 3, c = i & 7;
            const uint32_t sw = SW128((uint32_t)(r * 128 + c * 16));
            CP16(sb + K1_KHI + buf * 16384 + sw, khig + (size_t)(kt * 128 + r) * 128 + c * 16);
            CP16(sb + K1_KLO + buf * 16384 + sw, klog + (size_t)(kt * 128 + r) * 128 + c * 16);
        }
        CP_COMMIT;
    };
    issueK(0, 0);

    const int wm   = wid * 16;
    const int arow = lane & 15;
    const int abyt = (lane >> 4) << 4;
    const int row0 = lane >> 2;

    float m0 = -INFINITY, m1 = -INFINITY, l0 = 0.0f, l1 = 0.0f;

    const int* mp = mask + (size_t)b  * SEQ * SEQ;
    float*     ap = attn + (size_t)bh * SEQ * SEQ;

    for (int kt = 0; kt < 16; kt++) {
        if (kt + 1 < 16) { issueK(kt + 1, (kt + 1) & 1); CP_WAIT1; }
        else             { CP_WAIT0; }
        __syncthreads();

        const int buf = kt & 1;
        const uint32_t sqh = sb + K1_QHI, sql = sb + K1_QLO;
        const uint32_t skh = sb + K1_KHI + buf * 16384;
        const uint32_t skl = sb + K1_KLO + buf * 16384;

        float acc[16][4];
        #pragma unroll
        for (int j = 0; j < 16; j++)
            #pragma unroll
            for (int e = 0; e < 4; e++) acc[j][e] = 0.0f;

        #pragma unroll
        for (int ks = 0; ks < 4; ks++) {
            uint32_t ah[4], al[4];
            ldsm_x4(ah, sqh + SW128((uint32_t)((wm + arow) * 128 + ks * 32 + abyt)));
            ldsm_x4(al, sql + SW128((uint32_t)((wm + arow) * 128 + ks * 32 + abyt)));
            #pragma unroll
            for (int nj = 0; nj < 8; nj++) {
                uint32_t bh4[4], bl4[4];
                const uint32_t boff = SW128((uint32_t)((nj * 16 + arow) * 128 + ks * 32 + abyt));
                ldsm_x4(bh4, skh + boff);
                ldsm_x4(bl4, skl + boff);
                mma_bf16(acc[nj*2],   ah, bh4[0], bh4[2]);
                mma_bf16(acc[nj*2+1], ah, bh4[1], bh4[3]);
                mma_bf16(acc[nj*2],   ah, bl4[0], bl4[2]);
                mma_bf16(acc[nj*2+1], ah, bl4[1], bl4[3]);
                mma_bf16(acc[nj*2],   al, bh4[0], bh4[2]);
                mma_bf16(acc[nj*2+1], al, bh4[1], bh4[3]);
            }
        }

        // Mask + scale + store raw scores; track tile max.
        const int r0g = qBase + wm + row0;
        float tmx0 = -INFINITY, tmx1 = -INFINITY;
        #pragma unroll
        for (int j = 0; j < 16; j++) {
            const int col = kt * 128 + j * 8 + (lane & 3) * 2;
            const size_t o0 = (size_t)r0g * SEQ + col;
            const size_t o1 = o0 + (size_t)8 * SEQ;
            int2 ma = *(const int2*)&mp[o0];
            int2 mb = *(const int2*)&mp[o1];
            acc[j][0] = ma.x ? acc[j][0] * 0.125f : -1e9f;
            acc[j][1] = ma.y ? acc[j][1] * 0.125f : -1e9f;
            acc[j][2] = mb.x ? acc[j][2] * 0.125f : -1e9f;
            acc[j][3] = mb.y ? acc[j][3] * 0.125f : -1e9f;
            *(float2*)&ap[o0] = make_float2(acc[j][0], acc[j][1]);
            *(float2*)&ap[o1] = make_float2(acc[j][2], acc[j][3]);
            tmx0 = fmaxf(tmx0, fmaxf(acc[j][0], acc[j][1]));
            tmx1 = fmaxf(tmx1, fmaxf(acc[j][2], acc[j][3]));
        }
        tmx0 = fmaxf(tmx0, __shfl_xor_sync(0xffffffffu, tmx0, 1));
        tmx0 = fmaxf(tmx0, __shfl_xor_sync(0xffffffffu, tmx0, 2));
        tmx1 = fmaxf(tmx1, __shfl_xor_sync(0xffffffffu, tmx1, 1));
        tmx1 = fmaxf(tmx1, __shfl_xor_sync(0xffffffffu, tmx1, 2));

        const float m0n = fmaxf(m0, tmx0);
        const float m1n = fmaxf(m1, tmx1);
        float s0 = 0.0f, s1 = 0.0f;
        #pragma unroll
        for (int j = 0; j < 16; j++) {
            s0 += __expf(acc[j][0] - m0n) + __expf(acc[j][1] - m0n);
            s1 += __expf(acc[j][2] - m1n) + __expf(acc[j][3] - m1n);
        }
        s0 += __shfl_xor_sync(0xffffffffu, s0, 1);
        s0 += __shfl_xor_sync(0xffffffffu, s0, 2);
        s1 += __shfl_xor_sync(0xffffffffu, s1, 1);
        s1 += __shfl_xor_sync(0xffffffffu, s1, 2);

        l0 = l0 * __expf(m0 - m0n) + s0;  m0 = m0n;
        l1 = l1 * __expf(m1 - m1n) + s1;  m1 = m1n;

        __syncthreads();   // protect smem K buffer before reuse
    }

    if ((lane & 3) == 0) {
        const int r0g = qBase + wm + row0;
        g_M[(size_t)bh * SEQ + r0g]     = m0;
        g_L[(size_t)bh * SEQ + r0g]     = l0;
        g_M[(size_t)bh * SEQ + r0g + 8] = m1;
        g_L[(size_t)bh * SEQ + r0g + 8] = l1;
    }
}

// ---------------------------------------------------------------------------
// Kernel 2: normalize attn in place + out = P . V
// CTA: 128 threads, 64 q x 64 d; 32 k-tiles of 64. Warp tile 16q x 64d.
// V tiles cp.async double-buffered from preconverted g_Vhi/g_Vlo. SMEM ~49 KB.
// ---------------------------------------------------------------------------
#define K2_PHI 0
#define K2_PLO 8192
#define K2_VHI 16384    // + buf*8192 (bufs 16384, 24576)
#define K2_VLO 32768    // + buf*8192 (bufs 32768, 40960)
#define K2_M   49152
#define K2_IL  49408
#define K2_SMEM 49664

__global__ __launch_bounds__(128)
void out_norm(float* __restrict__ attn, float* __restrict__ out)
{
    extern __shared__ char smem[];
    const uint32_t sb = smem_u32(smem);
    const int tid = threadIdx.x, wid = tid >> 5, lane = tid & 31;

    const int bh = blockIdx.y;
    const int qBase = blockIdx.x * 64;

    float* ap = attn + (size_t)bh * SEQ * SEQ;

    float* sm_m  = (float*)(smem + K2_M);
    float* sm_il = (float*)(smem + K2_IL);
    if (tid < 64) {
        sm_m[tid]  = g_M[(size_t)bh * SEQ + qBase + tid];
        sm_il[tid] = 1.0f / g_L[(size_t)bh * SEQ + qBase + tid];
    }

    const char* vhig = (const char*)(g_Vhi + (size_t)bh * SEQ * DKDIM);
    const char* vlog = (const char*)(g_Vlo + (size_t)bh * SEQ * DKDIM);

    auto issueV = [&](int kt, int buf) {
        #pragma unroll
        for (int i = tid; i < 512; i += 128) {
            const int r = i >> 3, c = i & 7;
            const uint32_t sw = SW128((uint32_t)(r * 128 + c * 16));
            CP16(sb + K2_VHI + buf * 8192 + sw, vhig + (size_t)(kt * 64 + r) * 128 + c * 16);
            CP16(sb + K2_VLO + buf * 8192 + sw, vlog + (size_t)(kt * 64 + r) * 128 + c * 16);
        }
        CP_COMMIT;
    };
    issueV(0, 0);
    __syncthreads();   // sm_m/sm_il visible

    const int wm   = wid * 16;
    const int arow = lane & 15;
    const int abyt = (lane >> 4) << 4;

    float acc[8][4];
    #pragma unroll
    for (int j = 0; j < 8; j++)
        #pragma unroll
        for (int e = 0; e < 4; e++) acc[j][e] = 0.0f;

    for (int kt = 0; kt < 32; kt++) {
        if (kt + 1 < 32) issueV(kt + 1, (kt + 1) & 1);

        // Normalize raw scores tile [64 x 64]: exp, write attn, split into smem.
        #pragma unroll
        for (int j = 0; j < 8; j++) {
            const int slot = tid + j * 128;          // 0..1023
            const int r = slot >> 4, c4 = slot & 15;
            float* row = &ap[(size_t)(qBase + r) * SEQ + kt * 64 + c4 * 4];
            float4 v = *(const float4*)row;
            const float mr = sm_m[r], il = sm_il[r];
            v.x = __expf(v.x - mr) * il;
            v.y = __expf(v.y - mr) * il;
            v.z = __expf(v.z - mr) * il;
            v.w = __expf(v.w - mr) * il;
            *(float4*)row = v;
            uint16_t h0, l0, h1, l1, h2, l2, h3, l3;
            split_bf16(v.x, h0, l0); split_bf16(v.y, h1, l1);
            split_bf16(v.z, h2, l2); split_bf16(v.w, h3, l3);
            const uint32_t sw = SW128((uint32_t)(r * 128 + c4 * 8));
            *(uint32_t*)(smem + K2_PHI + sw)     = (uint32_t)h0 | ((uint32_t)h1 << 16);
            *(uint32_t*)(smem + K2_PHI + sw + 4) = (uint32_t)h2 | ((uint32_t)h3 << 16);
            *(uint32_t*)(smem + K2_PLO + sw)     = (uint32_t)l0 | ((uint32_t)l1 << 16);
            *(uint32_t*)(smem + K2_PLO + sw + 4) = (uint32_t)l2 | ((uint32_t)l3 << 16);
        }

        if (kt + 1 < 32) { CP_WAIT1; } else { CP_WAIT0; }
        __syncthreads();

        const int buf = kt & 1;
        const uint32_t sph = sb + K2_PHI, spl = sb + K2_PLO;
        const uint32_t svh = sb + K2_VHI + buf * 8192;
        const uint32_t svl = sb + K2_VLO + buf * 8192;

        #pragma unroll
        for (int ks = 0; ks < 4; ks++) {
            uint32_t ah[4], al[4];
            ldsm_x4(ah, sph + SW128((uint32_t)((wm + arow) * 128 + ks * 32 + abyt)));
            ldsm_x4(al, spl + SW128((uint32_t)((wm + arow) * 128 + ks * 32 + abyt)));
            #pragma unroll
            for (int ng = 0; ng < 4; ng++) {
                uint32_t bh4[4], bl4[4];
                const uint32_t boff = SW128((uint32_t)((ks * 16 + arow) * 128 + ng * 32 + abyt));
                ldsm_x4_t(bh4, svh + boff);
                ldsm_x4_t(bl4, svl + boff);
                mma_bf16(acc[ng*2],   ah, bh4[0], bh4[1]);
                mma_bf16(acc[ng*2+1], ah, bh4[2], bh4[3]);
                mma_bf16(acc[ng*2],   al, bh4[0], bh4[1]);
                mma_bf16(acc[ng*2+1], al, bh4[2], bh4[3]);
                mma_bf16(acc[ng*2],   ah, bl4[0], bl4[1]);
                mma_bf16(acc[ng*2+1], ah, bl4[2], bl4[3]);
            }
        }
        __syncthreads();   // P smem reused next iter
    }

    float* op = out + (size_t)bh * SEQ * DKDIM;
    const int r0 = qBase + wm + (lane >> 2);
    #pragma unroll
    for (int j = 0; j < 8; j++) {
        const int col = j * 8 + (lane & 3) * 2;
        *(float2*)&op[(size_t)r0 * DKDIM + col]       = make_float2(acc[j][0], acc[j][1]);
        *(float2*)&op[(size_t)(r0 + 8) * DKDIM + col] = make_float2(acc[j][2], acc[j][3]);
    }
}

// ---------------------------------------------------------------------------
extern "C" void kernel_launch(void* const* d_in, const int* in_sizes, int n_in,
                              void* d_out, int out_size)
{
    const float* Q    = (const float*)d_in[0];
    const float* K    = (const float*)d_in[1];
    const float* V    = (const float*)d_in[2];
    const int*   mask = (const int*)  d_in[3];

    float* out  = (float*)d_out;
    float* attn = out + (size_t)BH * SEQ * DKDIM;

    cudaFuncSetAttribute(scores_stats, cudaFuncAttributeMaxDynamicSharedMemorySize, K1_SMEM);
    cudaFuncSetAttribute(out_norm,     cudaFuncAttributeMaxDynamicSharedMemorySize, K2_SMEM);

    preconv<<<2048, 256>>>(Q, K, V);
    scores_stats<<<dim3(SEQ / 64, BH), 128, K1_SMEM>>>(mask, attn);
    out_norm<<<dim3(SEQ / 64, BH), 128, K2_SMEM>>>(attn, out);
}